// round 13
// baseline (speedup 1.0000x reference)
#include <cuda_runtime.h>
#include <cuda_bf16.h>
#include <math.h>
#include <cstdint>

#define B_      2
#define F_      16
#define H_      32
#define W_      32
#define HW      1024
#define NFRM    32
#define C_      320
#define CEXP    512
#define D_INNER 1024
#define NHEADS  16
#define HEADDIM 64
#define D_STATE 128
#define D_CONV  4
#define CONV_DIM 1280
#define D_IN_PROJ 2320
#define GROUPS  32
#define NSEQ    2048
#define L_      16
#define NTOK    32768

#define NP2320  2432
#define NPF     384

// ---------------- scratch ---------------------------------------------------
__device__ __nv_bfloat16 g_a0[(size_t)NTOK*C_];
__device__ __nv_bfloat16 g_zxb[(size_t)NTOK*D_IN_PROJ];
__device__ __nv_bfloat16 g_yb[(size_t)NTOK*D_INNER];
__device__ float         g_gst[NFRM*GROUPS*2];
__device__ __nv_bfloat16 g_w21t[NPF*CEXP];
__device__ __nv_bfloat16 g_wibf[(size_t)NP2320*CEXP];
__device__ __nv_bfloat16 g_wiall[(size_t)NP2320*C_];
__device__ __nv_bfloat16 g_wf1[NPF*CEXP];
__device__ __nv_bfloat16 g_opt[(size_t)D_INNER*CEXP];
__device__ __nv_bfloat16 g_wfall[(size_t)NPF*D_INNER];
__device__ float         g_b21[CEXP];
__device__ float         g_bi[D_IN_PROJ];
__device__ float         g_bf[C_];

// ---------------- PTX helpers ----------------------------------------------
__device__ __forceinline__ uint32_t smem_u32(const void* p) {
    uint32_t a;
    asm("{ .reg .u64 t; cvta.to.shared.u64 t, %1; cvt.u32.u64 %0, t; }" : "=r"(a) : "l"(p));
    return a;
}
__device__ __forceinline__ void cp16(uint32_t dst, const void* src) {
    asm volatile("cp.async.cg.shared.global [%0], [%1], 16;" :: "r"(dst), "l"(src) : "memory");
}
__device__ __forceinline__ void ldmx4(uint32_t addr, uint32_t& r0, uint32_t& r1,
                                      uint32_t& r2, uint32_t& r3) {
    asm volatile("ldmatrix.sync.aligned.m8n8.x4.shared.b16 {%0,%1,%2,%3}, [%4];"
                 : "=r"(r0), "=r"(r1), "=r"(r2), "=r"(r3) : "r"(addr));
}
__device__ __forceinline__ void mma16816(float* c, const uint32_t* a, const uint32_t* b) {
    asm volatile("mma.sync.aligned.m16n8k16.row.col.f32.bf16.bf16.f32 "
                 "{%0,%1,%2,%3}, {%4,%5,%6,%7}, {%8,%9}, {%0,%1,%2,%3};"
                 : "+f"(c[0]), "+f"(c[1]), "+f"(c[2]), "+f"(c[3])
                 : "r"(a[0]), "r"(a[1]), "r"(a[2]), "r"(a[3]), "r"(b[0]), "r"(b[1]));
}
__device__ __forceinline__ void storev2(float* p, float v0, float v1) { p[0] = v0; p[1] = v1; }
__device__ __forceinline__ void storev2(__nv_bfloat16* p, float v0, float v1) {
    __nv_bfloat162 t;
    t.x = __float2bfloat16(v0); t.y = __float2bfloat16(v1);
    *reinterpret_cast<__nv_bfloat162*>(p) = t;
}
// scalar SiLU: 1 MUFU
__device__ __forceinline__ float fast_silu(float x) {
    float t;
    asm("tanh.approx.f32 %0, %1;" : "=f"(t) : "f"(0.5f * x));
    return 0.5f * x * (1.f + t);
}
// packed bf16x2 SiLU: 1 MUFU for 2 elements
__device__ __forceinline__ __nv_bfloat162 silu2(__nv_bfloat162 x) {
    __nv_bfloat162 hx = __hmul2(x, __float2bfloat162_rn(0.5f));
    uint32_t hv = *reinterpret_cast<uint32_t*>(&hx), t;
    asm("tanh.approx.bf16x2 %0, %1;" : "=r"(t) : "r"(hv));
    __nv_bfloat162 th = *reinterpret_cast<__nv_bfloat162*>(&t);
    return __hmul2(hx, __hadd2(th, __float2bfloat162_rn(1.f)));
}

// row remap for fused permutes
template<int PERM> __device__ __forceinline__ int rowmap(int r) {
    if (PERM == 1) {
        int f = r & 15, hw = (r >> 4) & 1023, bb = r >> 14;
        return bb * 16384 + f * 1024 + hw;
    } else if (PERM == 2) {
        int hw = r & 1023, f = (r >> 10) & 15, bb = r >> 14;
        return bb * 16384 + hw * 16 + f;
    }
    return r;
}

// ---------------- bf16 HMMA GEMM (128x128x64, 3-stage) -----------------------
#define GEMM_SMEM (3*2*18432)   // 110592
template<typename OutT, int PERM>
__global__ void __launch_bounds__(256, 2)
tc_gemm(const __nv_bfloat16* __restrict__ A, const __nv_bfloat16* __restrict__ B,
        const float* __restrict__ bias, OutT* __restrict__ C, int M, int N, int K)
{
    extern __shared__ char smraw[];
    const uint32_t sbase = smem_u32(smraw);
    const int tid = threadIdx.x;
    const int lane = tid & 31, warp = tid >> 5;
    const int wm = (warp & 3) * 32, wn = (warp >> 2) * 64;
    const int m0 = blockIdx.y * 128, n0 = blockIdx.x * 128;

    const int seg = tid & 7, r0 = tid >> 3;
    int arows[4];
    #pragma unroll
    for (int j = 0; j < 4; ++j) arows[j] = rowmap<PERM>(m0 + r0 + j * 32);

    float acc[2][8][4];
    #pragma unroll
    for (int i = 0; i < 2; ++i)
        #pragma unroll
        for (int j = 0; j < 8; ++j)
            #pragma unroll
            for (int k = 0; k < 4; ++k) acc[i][j][k] = 0.f;

    const int nc = K >> 6;
    auto load = [&](int i) {
        const uint32_t da = sbase + (uint32_t)(i % 3) * 36864u;
        const uint32_t db = da + 18432u;
        const int k0 = i << 6;
        #pragma unroll
        for (int j = 0; j < 4; ++j) {
            int row = r0 + j * 32;
            uint32_t off = (uint32_t)row * 144u + (uint32_t)seg * 16u;
            cp16(da + off, A + (size_t)arows[j] * K + k0 + seg * 8);
            cp16(db + off, B + (size_t)(n0 + row) * K + k0 + seg * 8);
        }
        asm volatile("cp.async.commit_group;" ::: "memory");
    };

    load(0);
    if (nc > 1) load(1);

    for (int i = 0; i < nc; ++i) {
        if (i + 1 < nc) asm volatile("cp.async.wait_group 1;" ::: "memory");
        else            asm volatile("cp.async.wait_group 0;" ::: "memory");
        __syncthreads();
        if (i + 2 < nc) load(i + 2);

        const uint32_t sA  = sbase + (uint32_t)(i % 3) * 36864u;
        const uint32_t sBt = sA + 18432u;
        #pragma unroll
        for (int ks = 0; ks < 64; ks += 16) {
            uint32_t af[2][4];
            #pragma unroll
            for (int mt = 0; mt < 2; ++mt) {
                uint32_t addr = sA
                    + (uint32_t)(wm + mt * 16 + (lane & 15)) * 144u
                    + (uint32_t)(ks + ((lane >> 4) << 3)) * 2u;
                ldmx4(addr, af[mt][0], af[mt][1], af[mt][2], af[mt][3]);
            }
            uint32_t bf[8][2];
            #pragma unroll
            for (int nt2 = 0; nt2 < 4; ++nt2) {
                int n  = wn + nt2 * 16 + (lane & 7) + ((lane >> 4) << 3);
                int kk = ks + (((lane >> 3) & 1) << 3);
                uint32_t addr = sBt + (uint32_t)n * 144u + (uint32_t)kk * 2u;
                ldmx4(addr, bf[nt2*2][0], bf[nt2*2][1], bf[nt2*2+1][0], bf[nt2*2+1][1]);
            }
            #pragma unroll
            for (int mt = 0; mt < 2; ++mt)
                #pragma unroll
                for (int nt = 0; nt < 8; ++nt)
                    mma16816(acc[mt][nt], af[mt], bf[nt]);
        }
    }

    #pragma unroll
    for (int mt = 0; mt < 2; ++mt) {
        int row = m0 + wm + mt * 16 + (lane >> 2);
        #pragma unroll
        for (int nt = 0; nt < 8; ++nt) {
            int col = n0 + wn + nt * 8 + (lane & 3) * 2;
            if (col < N) {
                float b0 = bias ? bias[col]     : 0.f;
                float b1 = bias ? bias[col + 1] : 0.f;
                storev2(C + (size_t)row * N + col,       acc[mt][nt][0] + b0, acc[mt][nt][1] + b1);
                storev2(C + (size_t)(row + 8) * N + col, acc[mt][nt][2] + b0, acc[mt][nt][3] + b1);
            }
        }
    }
}

// ---------------- back GEMM fused with residual+transpose --------------------
__global__ void __launch_bounds__(256, 2)
tc_gemm_back(const __nv_bfloat16* __restrict__ A, const __nv_bfloat16* __restrict__ B,
             const float* __restrict__ bias, const float* __restrict__ x,
             const float* __restrict__ gamma, float* __restrict__ out, int K)
{
    extern __shared__ char smraw[];
    const uint32_t sbase = smem_u32(smraw);
    const int tid = threadIdx.x;
    const int lane = tid & 31, warp = tid >> 5;
    const int wm = (warp & 3) * 32, wn = (warp >> 2) * 64;
    const int m0 = blockIdx.y * 128, n0 = blockIdx.x * 128;

    const int seg = tid & 7, r0 = tid >> 3;
    int arows[4];
    #pragma unroll
    for (int j = 0; j < 4; ++j) arows[j] = rowmap<2>(m0 + r0 + j * 32);

    float acc[2][8][4];
    #pragma unroll
    for (int i = 0; i < 2; ++i)
        #pragma unroll
        for (int j = 0; j < 8; ++j)
            #pragma unroll
            for (int k = 0; k < 4; ++k) acc[i][j][k] = 0.f;

    const int nc = K >> 6;
    auto load = [&](int i) {
        const uint32_t da = sbase + (uint32_t)(i % 3) * 36864u;
        const uint32_t db = da + 18432u;
        const int k0 = i << 6;
        #pragma unroll
        for (int j = 0; j < 4; ++j) {
            int row = r0 + j * 32;
            uint32_t off = (uint32_t)row * 144u + (uint32_t)seg * 16u;
            cp16(da + off, A + (size_t)arows[j] * K + k0 + seg * 8);
            cp16(db + off, B + (size_t)(n0 + row) * K + k0 + seg * 8);
        }
        asm volatile("cp.async.commit_group;" ::: "memory");
    };

    load(0);
    if (nc > 1) load(1);

    for (int i = 0; i < nc; ++i) {
        if (i + 1 < nc) asm volatile("cp.async.wait_group 1;" ::: "memory");
        else            asm volatile("cp.async.wait_group 0;" ::: "memory");
        __syncthreads();
        if (i + 2 < nc) load(i + 2);

        const uint32_t sA  = sbase + (uint32_t)(i % 3) * 36864u;
        const uint32_t sBt = sA + 18432u;
        #pragma unroll
        for (int ks = 0; ks < 64; ks += 16) {
            uint32_t af[2][4];
            #pragma unroll
            for (int mt = 0; mt < 2; ++mt) {
                uint32_t addr = sA
                    + (uint32_t)(wm + mt * 16 + (lane & 15)) * 144u
                    + (uint32_t)(ks + ((lane >> 4) << 3)) * 2u;
                ldmx4(addr, af[mt][0], af[mt][1], af[mt][2], af[mt][3]);
            }
            uint32_t bf[8][2];
            #pragma unroll
            for (int nt2 = 0; nt2 < 4; ++nt2) {
                int n  = wn + nt2 * 16 + (lane & 7) + ((lane >> 4) << 3);
                int kk = ks + (((lane >> 3) & 1) << 3);
                uint32_t addr = sBt + (uint32_t)n * 144u + (uint32_t)kk * 2u;
                ldmx4(addr, bf[nt2*2][0], bf[nt2*2][1], bf[nt2*2+1][0], bf[nt2*2+1][1]);
            }
            #pragma unroll
            for (int mt = 0; mt < 2; ++mt)
                #pragma unroll
                for (int nt = 0; nt < 8; ++nt)
                    mma16816(acc[mt][nt], af[mt], bf[nt]);
        }
    }
    __syncthreads();

    float* tile = (float*)smraw;    // [128][129]
    #pragma unroll
    for (int mt = 0; mt < 2; ++mt) {
        int r = wm + mt * 16 + (lane >> 2);
        #pragma unroll
        for (int nt = 0; nt < 8; ++nt) {
            int cA = wn + nt * 8 + (lane & 3) * 2;
            int col = n0 + cA;
            float b0 = (col < C_)     ? bias[col]     : 0.f;
            float b1 = (col + 1 < C_) ? bias[col + 1] : 0.f;
            tile[cA * 129 + r]           = acc[mt][nt][0] + b0;
            tile[(cA + 1) * 129 + r]     = acc[mt][nt][1] + b1;
            tile[cA * 129 + r + 8]       = acc[mt][nt][2] + b0;
            tile[(cA + 1) * 129 + r + 8] = acc[mt][nt][3] + b1;
        }
    }
    __syncthreads();

    const int n = m0 >> 10, hw0 = m0 & 1023;
    const float gm = gamma[0];
    for (int i = tid; i < 128 * 128; i += 256) {
        int cc = i >> 7, hh = i & 127;
        int c = n0 + cc;
        if (c < C_) {
            size_t idx = ((size_t)n * C_ + c) * HW + hw0 + hh;
            out[idx] = x[idx] + gm * tile[cc * 129 + hh];
        }
    }
}

// ---------------- fused prep: gn_stats | w21t | wibf -------------------------
__global__ void fused_prep(const float* __restrict__ x, float* __restrict__ st,
                           const float* __restrict__ expand_w, const float* __restrict__ proj_in_w,
                           __nv_bfloat16* __restrict__ w21t,
                           const float* __restrict__ in_proj_w, __nv_bfloat16* __restrict__ wibf)
{
    const int z = blockIdx.z, bx = blockIdx.x, tid = threadIdx.x;
    if (z == 0) {
        if (bx >= NFRM * GROUPS) return;
        int n = bx >> 5, g = bx & 31;
        const int CPG = C_ / GROUPS;
        const float* base = x + ((size_t)n * C_ + g * CPG) * HW;
        float s = 0.f, ss = 0.f;
        for (int i = tid; i < CPG * HW; i += 256) { float v = base[i]; s += v; ss += v * v; }
        __shared__ float rs[256], rq[256];
        rs[tid] = s; rq[tid] = ss; __syncthreads();
        for (int o = 128; o > 0; o >>= 1) {
            if (tid < o) { rs[tid] += rs[tid + o]; rq[tid] += rq[tid + o]; }
            __syncthreads();
        }
        if (tid == 0) {
            float mean = rs[0] / (CPG * HW);
            float var  = rq[0] / (CPG * HW) - mean * mean;
            st[bx * 2]     = mean;
            st[bx * 2 + 1] = rsqrtf(var + 1e-5f);
        }
    } else if (z == 1) {
        if (bx >= 16 * 48) return;
        int lane = tid & 31, w = tid >> 5;
        int m = (bx & 15) * 32 + lane;
        int r = (bx >> 4) * 8 + w;
        float s = 0.f;
        if (r < C_) {
            const float* ar = expand_w + (size_t)m * C_;
            const float* bc = proj_in_w + r;
            for (int k = 0; k < C_; ++k) s += ar[k] * bc[(size_t)k * C_];
        }
        w21t[(size_t)r * CEXP + m] = __float2bfloat16(s);
    } else {
        int idx = bx * 256 + tid;
        wibf[idx] = __float2bfloat16(idx < D_IN_PROJ * CEXP ? in_proj_w[idx] : 0.f);
    }
}

// ---------------- fused back-weight prep: wf1 | opT | bfin -------------------
__global__ void back_prep(const float* __restrict__ proj_out_w, const float* __restrict__ collapse_w,
                          const float* __restrict__ collapse_b, const float* __restrict__ proj_out_b,
                          const float* __restrict__ out_proj_w, const float* __restrict__ rms,
                          __nv_bfloat16* __restrict__ wf1, __nv_bfloat16* __restrict__ opt,
                          float* __restrict__ bfin)
{
    const int z = blockIdx.z, bx = blockIdx.x, tid = threadIdx.x;
    if (z == 0) {
        // wf1[m,n] = sum_k proj_out[m,k]*collapse[k,n]; m<384pad, n<512
        if (bx >= 16 * 48) return;
        int lane = tid & 31, w = tid >> 5;
        int n = (bx & 15) * 32 + lane;
        int m = (bx >> 4) * 8 + w;
        if (m >= NPF) return;
        float s = 0.f;
        if (m < C_) {
            const float* ar = proj_out_w + (size_t)m * C_;
            const float* bc = collapse_w + n;
            for (int k = 0; k < C_; ++k) s += ar[k] * bc[(size_t)k * CEXP];
        }
        wf1[(size_t)m * CEXP + n] = __float2bfloat16(s);
    } else if (z == 1) {
        // opT[d,o] = out_proj[o,d]*rms[d]
        if (bx >= 16 * 32) return;
        __shared__ float t[32][33];
        int o0 = (bx & 15) * 32, d0 = (bx >> 4) * 32;
        int tx = tid & 31, ty = tid >> 5;
        #pragma unroll
        for (int r = 0; r < 4; ++r)
            t[ty + r * 8][tx] = out_proj_w[(size_t)(o0 + ty + r * 8) * D_INNER + d0 + tx];
        __syncthreads();
        #pragma unroll
        for (int r = 0; r < 4; ++r) {
            int d = d0 + ty + r * 8;
            opt[(size_t)d * CEXP + o0 + tx] = __float2bfloat16(t[tx][ty + r * 8] * rms[d]);
        }
    } else {
        // bfin[n] = proj_out@collapse_b + proj_out_b
        if (bx >= C_ / 8) return;
        int lane = tid & 31, w = tid >> 5;
        int n = bx * 8 + w;
        if (n >= C_) return;
        float s = 0.f;
        for (int k = lane; k < C_; k += 32) s += proj_out_w[(size_t)n * C_ + k] * collapse_b[k];
        #pragma unroll
        for (int off = 16; off > 0; off >>= 1) s += __shfl_xor_sync(0xffffffffu, s, off);
        if (lane == 0) bfin[n] = s + proj_out_b[n];
    }
}

// ---------------- bias fold --------------------------------------------------
__global__ void bfold_kernel(const float* __restrict__ W, const float* __restrict__ bin,
                             const float* __restrict__ badd, float* __restrict__ bout,
                             int N, int K) {
    int lane = threadIdx.x & 31, w = threadIdx.x >> 5;
    int n = blockIdx.x * 8 + w;
    if (n >= N) return;
    float s = 0.f;
    for (int k = lane; k < K; k += 32) s += W[(size_t)n * K + k] * bin[k];
    #pragma unroll
    for (int off = 16; off > 0; off >>= 1) s += __shfl_xor_sync(0xffffffffu, s, off);
    if (lane == 0) bout[n] = s + (badd ? badd[n] : 0.f);
}

// ---------------- GroupNorm apply --------------------------------------------
__global__ void gn_apply(const float* __restrict__ x, const float* __restrict__ st,
                         const float* __restrict__ w, const float* __restrict__ b,
                         __nv_bfloat16* __restrict__ out) {
    __shared__ float tile[32][33];
    int c0 = blockIdx.x * 32, hw0 = blockIdx.y * 32, n = blockIdx.z;
    int tx = threadIdx.x & 31, ty = threadIdx.x >> 5;
    #pragma unroll
    for (int r = 0; r < 4; ++r) {
        int c = c0 + ty + r * 8;
        int g = c / 10;
        float mean = st[(n * 32 + g) * 2], inv = st[(n * 32 + g) * 2 + 1];
        float v = x[((size_t)n * C_ + c) * HW + hw0 + tx];
        tile[ty + r * 8][tx] = (v - mean) * inv * w[c] + b[c];
    }
    __syncthreads();
    #pragma unroll
    for (int r = 0; r < 4; ++r) {
        int hw = hw0 + ty + r * 8;
        out[((size_t)n * HW + hw) * C_ + c0 + tx] = __float2bfloat16(tile[tx][ty + r * 8]);
    }
}

// ---------------- fused dt + conv + SSM + gate + RMSNorm ---------------------
// bf16x2 packed SiLU (tanh.approx.bf16x2): 1 MUFU / 2 elems.
#define CDP 1282
#define MAMBA_SMEM 94336
__global__ void __launch_bounds__(512)
mamba_fused(const __nv_bfloat16* __restrict__ zx, const float* __restrict__ bi,
            const float* __restrict__ cw, const float* __restrict__ cb,
            const float* __restrict__ dt_bias, const float* __restrict__ A_log,
            const float* __restrict__ Dv, __nv_bfloat16* __restrict__ yb)
{
    extern __shared__ char sm[];
    __nv_bfloat16* sx = (__nv_bfloat16*)sm;                 // [16][1282]
    __nv_bfloat16* sy = (__nv_bfloat16*)(sm + 41024);       // [16][1024]
    float* sW     = (float*)(sm + 73792);                   // [16][16][16]
    float* sScore = (float*)(sm + 90176);
    float* sDt    = (float*)(sm + 91200);
    float* sEl    = (float*)(sm + 92224);
    float* sEdt   = (float*)(sm + 93248);
    float* sSq    = (float*)(sm + 94272);
    const int s = blockIdx.x, tid = threadIdx.x;
    const __nv_bfloat16* zb = zx + (size_t)s * L_ * D_IN_PROJ;

    if (tid < 256) {
        int l = tid >> 4, h = tid & 15;
        float v = __bfloat162float(zb[(size_t)l * D_IN_PROJ + 2304 + h]) + bi[2304 + h] + dt_bias[h];
        sDt[l * 16 + h] = (v > 20.f) ? v : log1pf(__expf(v));
    }
    if (tid < 16) sSq[tid] = 0.f;

    // conv: channel pairs, packed SiLU
    for (int p = tid; p < CONV_DIM / 2; p += 512) {
        const int c = p * 2;
        float wa0 = cw[c*4],   wa1 = cw[c*4+1], wa2 = cw[c*4+2], wa3 = cw[c*4+3];
        float wb0 = cw[c*4+4], wb1 = cw[c*4+5], wb2 = cw[c*4+6], wb3 = cw[c*4+7];
        float ba = cb[c] + 0.f, bbv = cb[c+1];
        float bia = bi[D_INNER + c], bib = bi[D_INNER + c + 1];
        float a0h = 0.f, a1h = 0.f, a2h = 0.f;   // history channel c
        float b0h = 0.f, b1h = 0.f, b2h = 0.f;   // history channel c+1
        const __nv_bfloat162* base = (const __nv_bfloat162*)(zb + D_INNER + c);
        #pragma unroll
        for (int l = 0; l < L_; ++l) {
            __nv_bfloat162 v = base[(size_t)l * (D_IN_PROJ / 2)];
            float a3 = __bfloat162float(v.x) + bia;
            float b3 = __bfloat162float(v.y) + bib;
            float oa = a0h*wa0 + a1h*wa1 + a2h*wa2 + a3*wa3 + ba;
            float ob = b0h*wb0 + b1h*wb1 + b2h*wb2 + b3*wb3 + bbv;
            __nv_bfloat162 r = silu2(__floats2bfloat162_rn(oa, ob));
            *(__nv_bfloat162*)(sx + l * CDP + c) = r;
            a0h = a1h; a1h = a2h; a2h = a3;
            b0h = b1h; b1h = b2h; b2h = b3;
        }
    }
    __syncthreads();

    if (tid < 256) {
        int l = tid >> 4, sp = tid & 15;
        float acc = 0.f;
        #pragma unroll 8
        for (int n = 0; n < D_STATE; ++n)
            acc += __bfloat162float(sx[l * CDP + D_INNER + D_STATE + n])
                 * __bfloat162float(sx[sp * CDP + D_INNER + n]);
        sScore[l * 16 + sp] = acc;
    } else if (tid < 272) {
        int h = tid - 256;
        float a = -expf(A_log[h]);
        float run = 0.f;
        #pragma unroll
        for (int l = 0; l < L_; ++l) {
            run += sDt[l * 16 + h] * a;
            sEl [l * 16 + h] = expf(run);
            sEdt[l * 16 + h] = expf(-run) * sDt[l * 16 + h];
        }
    }
    __syncthreads();

    for (int i = tid; i < NHEADS * 256; i += 512) {
        int h = i >> 8, l = (i >> 4) & 15, sp = i & 15;
        float w;
        if (sp < l)       w = sScore[l*16+sp] * (sEl[l*16+h] * sEdt[sp*16+h]);
        else if (sp == l) w = sScore[l*16+l] * sDt[l*16+h] + Dv[h];
        else              w = 0.f;
        sW[(h * 16 + l) * 16 + sp] = w;
    }
    __syncthreads();

    const int h = tid >> 5, lane = tid & 31;
    const float bz0 = bi[h * HEADDIM + lane];
    const float bz1 = bi[h * HEADDIM + lane + 32];
    float x0[L_], x1[L_];
    #pragma unroll
    for (int sp = 0; sp < L_; ++sp) {
        x0[sp] = __bfloat162float(sx[sp * CDP + h * HEADDIM + lane]);
        x1[sp] = __bfloat162float(sx[sp * CDP + h * HEADDIM + lane + 32]);
    }
    #pragma unroll
    for (int l = 0; l < L_; ++l) {
        float a0 = 0.f, a1 = 0.f;
        for (int sp = 0; sp <= l; ++sp) {
            float w = sW[(h * 16 + l) * 16 + sp];
            a0 += w * x0[sp]; a1 += w * x1[sp];
        }
        float z0 = __bfloat162float(zb[(size_t)l * D_IN_PROJ + h * HEADDIM + lane]) + bz0;
        float z1 = __bfloat162float(zb[(size_t)l * D_IN_PROJ + h * HEADDIM + lane + 32]) + bz1;
        __nv_bfloat162 sg = silu2(__floats2bfloat162_rn(z0, z1));
        a0 *= __bfloat162float(sg.x);
        a1 *= __bfloat162float(sg.y);
        sy[l * 1024 + h * HEADDIM + lane]      = __float2bfloat16(a0);
        sy[l * 1024 + h * HEADDIM + lane + 32] = __float2bfloat16(a1);
        float q = a0 * a0 + a1 * a1;
        #pragma unroll
        for (int off = 16; off > 0; off >>= 1) q += __shfl_xor_sync(0xffffffffu, q, off);
        if (lane == 0) atomicAdd(&sSq[l], q);
    }
    __syncthreads();
    if (tid < 16) sSq[tid] = rsqrtf(sSq[tid] / (float)D_INNER + 1e-5f);
    __syncthreads();

    __nv_bfloat16* ob = yb + (size_t)s * L_ * D_INNER;
    for (int i = tid; i < L_ * D_INNER; i += 512) {
        int l = i >> 10;
        ob[i] = __float2bfloat16(__bfloat162float(sy[i]) * sSq[l]);
    }
}

// ---------------- launch -------------------------------------------------------
extern "C" void kernel_launch(void* const* d_in, const int* in_sizes, int n_in,
                              void* d_out, int out_size) {
    const float* x          = (const float*)d_in[0];
    const float* norm_w     = (const float*)d_in[1];
    const float* norm_b     = (const float*)d_in[2];
    const float* proj_in_w  = (const float*)d_in[3];
    const float* proj_in_b  = (const float*)d_in[4];
    const float* expand_w   = (const float*)d_in[5];
    const float* expand_b   = (const float*)d_in[6];
    const float* in_proj_w  = (const float*)d_in[7];
    const float* conv_w     = (const float*)d_in[8];
    const float* conv_b     = (const float*)d_in[9];
    const float* dt_bias    = (const float*)d_in[10];
    const float* A_log      = (const float*)d_in[11];
    const float* Dv         = (const float*)d_in[12];
    const float* rms_w      = (const float*)d_in[13];
    const float* out_proj_w = (const float*)d_in[14];
    const float* collapse_w = (const float*)d_in[15];
    const float* collapse_b = (const float*)d_in[16];
    const float* proj_out_w = (const float*)d_in[17];
    const float* proj_out_b = (const float*)d_in[18];
    const float* gamma      = (const float*)d_in[19];

    __nv_bfloat16 *a0, *zxb, *yb, *w21t, *wibf, *wiall, *wf1, *opt, *wfall;
    float *gst, *b21, *bi, *bfin;
    cudaGetSymbolAddress((void**)&a0,   g_a0);   cudaGetSymbolAddress((void**)&zxb,  g_zxb);
    cudaGetSymbolAddress((void**)&yb,   g_yb);   cudaGetSymbolAddress((void**)&gst,  g_gst);
    cudaGetSymbolAddress((void**)&w21t, g_w21t); cudaGetSymbolAddress((void**)&wibf, g_wibf);
    cudaGetSymbolAddress((void**)&wiall,g_wiall);cudaGetSymbolAddress((void**)&wf1,  g_wf1);
    cudaGetSymbolAddress((void**)&opt,  g_opt);  cudaGetSymbolAddress((void**)&wfall,g_wfall);
    cudaGetSymbolAddress((void**)&b21,  g_b21);  cudaGetSymbolAddress((void**)&bi,   g_bi);
    cudaGetSymbolAddress((void**)&bfin, g_bf);

    cudaFuncSetAttribute((const void*)tc_gemm<__nv_bfloat16,0>, cudaFuncAttributeMaxDynamicSharedMemorySize, GEMM_SMEM);
    cudaFuncSetAttribute((const void*)tc_gemm<__nv_bfloat16,1>, cudaFuncAttributeMaxDynamicSharedMemorySize, GEMM_SMEM);
    cudaFuncSetAttribute((const void*)tc_gemm_back,             cudaFuncAttributeMaxDynamicSharedMemorySize, GEMM_SMEM);
    cudaFuncSetAttribute((const void*)mamba_fused,              cudaFuncAttributeMaxDynamicSharedMemorySize, MAMBA_SMEM);

    { dim3 g(4864, 1, 3);
      fused_prep<<<g, 256>>>(x, gst, expand_w, proj_in_w, w21t, in_proj_w, wibf); }
    { dim3 g(C_/32, HW/32, NFRM); gn_apply<<<g, 256>>>(x, gst, norm_w, norm_b, a0); }
    { dim3 g(NPF/128, NP2320/128);
      tc_gemm<__nv_bfloat16,0><<<g, 256, GEMM_SMEM>>>(wibf, w21t, nullptr, wiall, NP2320, C_, CEXP); }
    { dim3 g(NP2320/128, NTOK/128);
      tc_gemm<__nv_bfloat16,1><<<g, 256, GEMM_SMEM>>>(a0, wiall, nullptr, zxb, NTOK, D_IN_PROJ, C_); }
    bfold_kernel<<<CEXP/8, 256>>>(expand_w, proj_in_b, expand_b, b21, CEXP, C_);
    bfold_kernel<<<(D_IN_PROJ+7)/8, 256>>>(in_proj_w, b21, nullptr, bi, D_IN_PROJ, CEXP);
    mamba_fused<<<NSEQ, 512, MAMBA_SMEM>>>(zxb, bi, conv_w, conv_b, dt_bias, A_log, Dv, yb);
    { dim3 g(768, 1, 3);
      back_prep<<<g, 256>>>(proj_out_w, collapse_w, collapse_b, proj_out_b,
                            out_proj_w, rms_w, wf1, opt, bfin); }
    { dim3 g(D_INNER/128, NPF/128);
      tc_gemm<__nv_bfloat16,0><<<g, 256, GEMM_SMEM>>>(wf1, opt, nullptr, wfall, NPF, D_INNER, CEXP); }
    { dim3 g(NPF/128, NTOK/128);
      tc_gemm_back<<<g, 256, GEMM_SMEM>>>(yb, wfall, bfin, x, gamma, (float*)d_out, D_INNER); }
}

// round 14
// speedup vs baseline: 1.1170x; 1.1170x over previous
#include <cuda_runtime.h>
#include <cuda_bf16.h>
#include <math.h>
#include <cstdint>

#define B_      2
#define F_      16
#define H_      32
#define W_      32
#define HW      1024
#define NFRM    32
#define C_      320
#define CEXP    512
#define D_INNER 1024
#define NHEADS  16
#define HEADDIM 64
#define D_STATE 128
#define D_CONV  4
#define CONV_DIM 1280
#define D_IN_PROJ 2320
#define GROUPS  32
#define NSEQ    2048
#define L_      16
#define NTOK    32768

#define NP2320  2432
#define NPF     384

// ---------------- scratch ---------------------------------------------------
__device__ __nv_bfloat16 g_a0[(size_t)NTOK*C_];
__device__ __nv_bfloat16 g_zxb[(size_t)NTOK*D_IN_PROJ];
__device__ __nv_bfloat16 g_yb[(size_t)NTOK*D_INNER];
__device__ __nv_bfloat16 g_w21t[NPF*CEXP];
__device__ __nv_bfloat16 g_wibf[(size_t)NP2320*CEXP];
__device__ __nv_bfloat16 g_wiall[(size_t)NP2320*C_];
__device__ __nv_bfloat16 g_wf1[NPF*CEXP];
__device__ __nv_bfloat16 g_opt[(size_t)D_INNER*CEXP];
__device__ __nv_bfloat16 g_wfall[(size_t)NPF*D_INNER];
__device__ float         g_b21[CEXP];
__device__ float         g_bi[D_IN_PROJ];
__device__ float         g_bf[C_];

// ---------------- PTX helpers ----------------------------------------------
__device__ __forceinline__ uint32_t smem_u32(const void* p) {
    uint32_t a;
    asm("{ .reg .u64 t; cvta.to.shared.u64 t, %1; cvt.u32.u64 %0, t; }" : "=r"(a) : "l"(p));
    return a;
}
__device__ __forceinline__ void cp16(uint32_t dst, const void* src) {
    asm volatile("cp.async.cg.shared.global [%0], [%1], 16;" :: "r"(dst), "l"(src) : "memory");
}
__device__ __forceinline__ void ldmx4(uint32_t addr, uint32_t& r0, uint32_t& r1,
                                      uint32_t& r2, uint32_t& r3) {
    asm volatile("ldmatrix.sync.aligned.m8n8.x4.shared.b16 {%0,%1,%2,%3}, [%4];"
                 : "=r"(r0), "=r"(r1), "=r"(r2), "=r"(r3) : "r"(addr));
}
__device__ __forceinline__ void mma16816(float* c, const uint32_t* a, const uint32_t* b) {
    asm volatile("mma.sync.aligned.m16n8k16.row.col.f32.bf16.bf16.f32 "
                 "{%0,%1,%2,%3}, {%4,%5,%6,%7}, {%8,%9}, {%0,%1,%2,%3};"
                 : "+f"(c[0]), "+f"(c[1]), "+f"(c[2]), "+f"(c[3])
                 : "r"(a[0]), "r"(a[1]), "r"(a[2]), "r"(a[3]), "r"(b[0]), "r"(b[1]));
}
__device__ __forceinline__ void storev2(float* p, float v0, float v1) { p[0] = v0; p[1] = v1; }
__device__ __forceinline__ void storev2(__nv_bfloat16* p, float v0, float v1) {
    __nv_bfloat162 t;
    t.x = __float2bfloat16(v0); t.y = __float2bfloat16(v1);
    *reinterpret_cast<__nv_bfloat162*>(p) = t;
}
// scalar SiLU: 1 MUFU
__device__ __forceinline__ float fast_silu(float x) {
    float t;
    asm("tanh.approx.f32 %0, %1;" : "=f"(t) : "f"(0.5f * x));
    return 0.5f * x * (1.f + t);
}

// row remap for fused permutes
template<int PERM> __device__ __forceinline__ int rowmap(int r) {
    if (PERM == 1) {
        int f = r & 15, hw = (r >> 4) & 1023, bb = r >> 14;
        return bb * 16384 + f * 1024 + hw;
    } else if (PERM == 2) {
        int hw = r & 1023, f = (r >> 10) & 15, bb = r >> 14;
        return bb * 16384 + hw * 16 + f;
    }
    return r;
}

// ---------------- bf16 HMMA GEMM (128x128x64, 3-stage) -----------------------
#define GEMM_SMEM (3*2*18432)   // 110592
template<typename OutT, int PERM>
__global__ void __launch_bounds__(256, 2)
tc_gemm(const __nv_bfloat16* __restrict__ A, const __nv_bfloat16* __restrict__ B,
        const float* __restrict__ bias, OutT* __restrict__ C, int M, int N, int K)
{
    extern __shared__ char smraw[];
    const uint32_t sbase = smem_u32(smraw);
    const int tid = threadIdx.x;
    const int lane = tid & 31, warp = tid >> 5;
    const int wm = (warp & 3) * 32, wn = (warp >> 2) * 64;
    const int m0 = blockIdx.y * 128, n0 = blockIdx.x * 128;

    const int seg = tid & 7, r0 = tid >> 3;
    int arows[4];
    #pragma unroll
    for (int j = 0; j < 4; ++j) arows[j] = rowmap<PERM>(m0 + r0 + j * 32);

    float acc[2][8][4];
    #pragma unroll
    for (int i = 0; i < 2; ++i)
        #pragma unroll
        for (int j = 0; j < 8; ++j)
            #pragma unroll
            for (int k = 0; k < 4; ++k) acc[i][j][k] = 0.f;

    const int nc = K >> 6;
    auto load = [&](int i) {
        const uint32_t da = sbase + (uint32_t)(i % 3) * 36864u;
        const uint32_t db = da + 18432u;
        const int k0 = i << 6;
        #pragma unroll
        for (int j = 0; j < 4; ++j) {
            int row = r0 + j * 32;
            uint32_t off = (uint32_t)row * 144u + (uint32_t)seg * 16u;
            cp16(da + off, A + (size_t)arows[j] * K + k0 + seg * 8);
            cp16(db + off, B + (size_t)(n0 + row) * K + k0 + seg * 8);
        }
        asm volatile("cp.async.commit_group;" ::: "memory");
    };

    load(0);
    if (nc > 1) load(1);

    for (int i = 0; i < nc; ++i) {
        if (i + 1 < nc) asm volatile("cp.async.wait_group 1;" ::: "memory");
        else            asm volatile("cp.async.wait_group 0;" ::: "memory");
        __syncthreads();
        if (i + 2 < nc) load(i + 2);

        const uint32_t sA  = sbase + (uint32_t)(i % 3) * 36864u;
        const uint32_t sBt = sA + 18432u;
        #pragma unroll
        for (int ks = 0; ks < 64; ks += 16) {
            uint32_t af[2][4];
            #pragma unroll
            for (int mt = 0; mt < 2; ++mt) {
                uint32_t addr = sA
                    + (uint32_t)(wm + mt * 16 + (lane & 15)) * 144u
                    + (uint32_t)(ks + ((lane >> 4) << 3)) * 2u;
                ldmx4(addr, af[mt][0], af[mt][1], af[mt][2], af[mt][3]);
            }
            uint32_t bf[8][2];
            #pragma unroll
            for (int nt2 = 0; nt2 < 4; ++nt2) {
                int n  = wn + nt2 * 16 + (lane & 7) + ((lane >> 4) << 3);
                int kk = ks + (((lane >> 3) & 1) << 3);
                uint32_t addr = sBt + (uint32_t)n * 144u + (uint32_t)kk * 2u;
                ldmx4(addr, bf[nt2*2][0], bf[nt2*2][1], bf[nt2*2+1][0], bf[nt2*2+1][1]);
            }
            #pragma unroll
            for (int mt = 0; mt < 2; ++mt)
                #pragma unroll
                for (int nt = 0; nt < 8; ++nt)
                    mma16816(acc[mt][nt], af[mt], bf[nt]);
        }
    }

    #pragma unroll
    for (int mt = 0; mt < 2; ++mt) {
        int row = m0 + wm + mt * 16 + (lane >> 2);
        #pragma unroll
        for (int nt = 0; nt < 8; ++nt) {
            int col = n0 + wn + nt * 8 + (lane & 3) * 2;
            if (col < N) {
                float b0 = bias ? bias[col]     : 0.f;
                float b1 = bias ? bias[col + 1] : 0.f;
                storev2(C + (size_t)row * N + col,       acc[mt][nt][0] + b0, acc[mt][nt][1] + b1);
                storev2(C + (size_t)(row + 8) * N + col, acc[mt][nt][2] + b0, acc[mt][nt][3] + b1);
            }
        }
    }
}

// ---------------- back GEMM fused with residual+transpose --------------------
__global__ void __launch_bounds__(256, 2)
tc_gemm_back(const __nv_bfloat16* __restrict__ A, const __nv_bfloat16* __restrict__ B,
             const float* __restrict__ bias, const float* __restrict__ x,
             const float* __restrict__ gamma, float* __restrict__ out, int K)
{
    extern __shared__ char smraw[];
    const uint32_t sbase = smem_u32(smraw);
    const int tid = threadIdx.x;
    const int lane = tid & 31, warp = tid >> 5;
    const int wm = (warp & 3) * 32, wn = (warp >> 2) * 64;
    const int m0 = blockIdx.y * 128, n0 = blockIdx.x * 128;

    const int seg = tid & 7, r0 = tid >> 3;
    int arows[4];
    #pragma unroll
    for (int j = 0; j < 4; ++j) arows[j] = rowmap<2>(m0 + r0 + j * 32);

    float acc[2][8][4];
    #pragma unroll
    for (int i = 0; i < 2; ++i)
        #pragma unroll
        for (int j = 0; j < 8; ++j)
            #pragma unroll
            for (int k = 0; k < 4; ++k) acc[i][j][k] = 0.f;

    const int nc = K >> 6;
    auto load = [&](int i) {
        const uint32_t da = sbase + (uint32_t)(i % 3) * 36864u;
        const uint32_t db = da + 18432u;
        const int k0 = i << 6;
        #pragma unroll
        for (int j = 0; j < 4; ++j) {
            int row = r0 + j * 32;
            uint32_t off = (uint32_t)row * 144u + (uint32_t)seg * 16u;
            cp16(da + off, A + (size_t)arows[j] * K + k0 + seg * 8);
            cp16(db + off, B + (size_t)(n0 + row) * K + k0 + seg * 8);
        }
        asm volatile("cp.async.commit_group;" ::: "memory");
    };

    load(0);
    if (nc > 1) load(1);

    for (int i = 0; i < nc; ++i) {
        if (i + 1 < nc) asm volatile("cp.async.wait_group 1;" ::: "memory");
        else            asm volatile("cp.async.wait_group 0;" ::: "memory");
        __syncthreads();
        if (i + 2 < nc) load(i + 2);

        const uint32_t sA  = sbase + (uint32_t)(i % 3) * 36864u;
        const uint32_t sBt = sA + 18432u;
        #pragma unroll
        for (int ks = 0; ks < 64; ks += 16) {
            uint32_t af[2][4];
            #pragma unroll
            for (int mt = 0; mt < 2; ++mt) {
                uint32_t addr = sA
                    + (uint32_t)(wm + mt * 16 + (lane & 15)) * 144u
                    + (uint32_t)(ks + ((lane >> 4) << 3)) * 2u;
                ldmx4(addr, af[mt][0], af[mt][1], af[mt][2], af[mt][3]);
            }
            uint32_t bf[8][2];
            #pragma unroll
            for (int nt2 = 0; nt2 < 4; ++nt2) {
                int n  = wn + nt2 * 16 + (lane & 7) + ((lane >> 4) << 3);
                int kk = ks + (((lane >> 3) & 1) << 3);
                uint32_t addr = sBt + (uint32_t)n * 144u + (uint32_t)kk * 2u;
                ldmx4(addr, bf[nt2*2][0], bf[nt2*2][1], bf[nt2*2+1][0], bf[nt2*2+1][1]);
            }
            #pragma unroll
            for (int mt = 0; mt < 2; ++mt)
                #pragma unroll
                for (int nt = 0; nt < 8; ++nt)
                    mma16816(acc[mt][nt], af[mt], bf[nt]);
        }
    }
    __syncthreads();

    float* tile = (float*)smraw;    // [128][129]
    #pragma unroll
    for (int mt = 0; mt < 2; ++mt) {
        int r = wm + mt * 16 + (lane >> 2);
        #pragma unroll
        for (int nt = 0; nt < 8; ++nt) {
            int cA = wn + nt * 8 + (lane & 3) * 2;
            int col = n0 + cA;
            float b0 = (col < C_)     ? bias[col]     : 0.f;
            float b1 = (col + 1 < C_) ? bias[col + 1] : 0.f;
            tile[cA * 129 + r]           = acc[mt][nt][0] + b0;
            tile[(cA + 1) * 129 + r]     = acc[mt][nt][1] + b1;
            tile[cA * 129 + r + 8]       = acc[mt][nt][2] + b0;
            tile[(cA + 1) * 129 + r + 8] = acc[mt][nt][3] + b1;
        }
    }
    __syncthreads();

    const int n = m0 >> 10, hw0 = m0 & 1023;
    const float gm = gamma[0];
    for (int i = tid; i < 128 * 128; i += 256) {
        int cc = i >> 7, hh = i & 127;
        int c = n0 + cc;
        if (c < C_) {
            size_t idx = ((size_t)n * C_ + c) * HW + hw0 + hh;
            out[idx] = x[idx] + gm * tile[cc * 129 + hh];
        }
    }
}

// ---------------- single-pass GroupNorm (stats + apply + transpose) ----------
// one block per (frame, group): 10 channels x 1024 hw cached in padded smem.
__global__ void __launch_bounds__(256) gn_fused(
    const float* __restrict__ x, const float* __restrict__ w,
    const float* __restrict__ b, __nv_bfloat16* __restrict__ out)
{
    __shared__ float buf[10 * 1025];
    __shared__ float rs[8], rq[8];
    __shared__ float sw[10], sb[10];
    const int n = blockIdx.x >> 5, g = blockIdx.x & 31;
    const int tid = threadIdx.x, lane = tid & 31, warp = tid >> 5;
    const float* base = x + ((size_t)n * C_ + g * 10) * HW;

    if (tid < 10) { sw[tid] = w[g * 10 + tid]; sb[tid] = b[g * 10 + tid]; }

    float s = 0.f, ss = 0.f;
    for (int i = tid; i < 10 * HW; i += 256) {
        float v = base[i];
        buf[(i >> 10) * 1025 + (i & 1023)] = v;
        s += v; ss += v * v;
    }
    #pragma unroll
    for (int o = 16; o > 0; o >>= 1) {
        s  += __shfl_xor_sync(0xffffffffu, s,  o);
        ss += __shfl_xor_sync(0xffffffffu, ss, o);
    }
    if (lane == 0) { rs[warp] = s; rq[warp] = ss; }
    __syncthreads();
    if (tid == 0) {
        float ts = 0.f, tq = 0.f;
        #pragma unroll
        for (int i = 0; i < 8; ++i) { ts += rs[i]; tq += rq[i]; }
        float mean = ts / (10.f * HW);
        float var  = tq / (10.f * HW) - mean * mean;
        rs[0] = mean;
        rq[0] = rsqrtf(var + 1e-5f);
    }
    __syncthreads();
    const float mean = rs[0], inv = rq[0];

    // write token-major: out[(n*HW+hw)*C_ + g*10 + cl]
    for (int i = tid; i < 10 * HW; i += 256) {
        int cl = i % 10, hw = i / 10;
        float v = (buf[cl * 1025 + hw] - mean) * inv * sw[cl] + sb[cl];
        out[((size_t)n * HW + hw) * C_ + g * 10 + cl] = __float2bfloat16(v);
    }
}

// ---------------- fused prep: w21t | wibf ------------------------------------
__global__ void fused_prep(const float* __restrict__ expand_w, const float* __restrict__ proj_in_w,
                           __nv_bfloat16* __restrict__ w21t,
                           const float* __restrict__ in_proj_w, __nv_bfloat16* __restrict__ wibf)
{
    const int z = blockIdx.z, bx = blockIdx.x, tid = threadIdx.x;
    if (z == 0) {
        if (bx >= 16 * 48) return;
        int lane = tid & 31, w = tid >> 5;
        int m = (bx & 15) * 32 + lane;
        int r = (bx >> 4) * 8 + w;
        float s = 0.f;
        if (r < C_) {
            const float* ar = expand_w + (size_t)m * C_;
            const float* bc = proj_in_w + r;
            for (int k = 0; k < C_; ++k) s += ar[k] * bc[(size_t)k * C_];
        }
        w21t[(size_t)r * CEXP + m] = __float2bfloat16(s);
    } else {
        int idx = bx * 256 + tid;
        if (idx < NP2320 * CEXP)
            wibf[idx] = __float2bfloat16(idx < D_IN_PROJ * CEXP ? in_proj_w[idx] : 0.f);
    }
}

// ---------------- fused back-weight prep: wf1 | opT | bfin -------------------
__global__ void back_prep(const float* __restrict__ proj_out_w, const float* __restrict__ collapse_w,
                          const float* __restrict__ collapse_b, const float* __restrict__ proj_out_b,
                          const float* __restrict__ out_proj_w, const float* __restrict__ rms,
                          __nv_bfloat16* __restrict__ wf1, __nv_bfloat16* __restrict__ opt,
                          float* __restrict__ bfin)
{
    const int z = blockIdx.z, bx = blockIdx.x, tid = threadIdx.x;
    if (z == 0) {
        if (bx >= 16 * 48) return;
        int lane = tid & 31, w = tid >> 5;
        int n = (bx & 15) * 32 + lane;
        int m = (bx >> 4) * 8 + w;
        if (m >= NPF) return;
        float s = 0.f;
        if (m < C_) {
            const float* ar = proj_out_w + (size_t)m * C_;
            const float* bc = collapse_w + n;
            for (int k = 0; k < C_; ++k) s += ar[k] * bc[(size_t)k * CEXP];
        }
        wf1[(size_t)m * CEXP + n] = __float2bfloat16(s);
    } else if (z == 1) {
        if (bx >= 16 * 32) return;
        __shared__ float t[32][33];
        int o0 = (bx & 15) * 32, d0 = (bx >> 4) * 32;
        int tx = tid & 31, ty = tid >> 5;
        #pragma unroll
        for (int r = 0; r < 4; ++r)
            t[ty + r * 8][tx] = out_proj_w[(size_t)(o0 + ty + r * 8) * D_INNER + d0 + tx];
        __syncthreads();
        #pragma unroll
        for (int r = 0; r < 4; ++r) {
            int d = d0 + ty + r * 8;
            opt[(size_t)d * CEXP + o0 + tx] = __float2bfloat16(t[tx][ty + r * 8] * rms[d]);
        }
    } else {
        if (bx >= C_ / 8) return;
        int lane = tid & 31, w = tid >> 5;
        int n = bx * 8 + w;
        if (n >= C_) return;
        float s = 0.f;
        for (int k = lane; k < C_; k += 32) s += proj_out_w[(size_t)n * C_ + k] * collapse_b[k];
        #pragma unroll
        for (int off = 16; off > 0; off >>= 1) s += __shfl_xor_sync(0xffffffffu, s, off);
        if (lane == 0) bfin[n] = s + proj_out_b[n];
    }
}

// ---------------- bias fold --------------------------------------------------
__global__ void bfold_kernel(const float* __restrict__ W, const float* __restrict__ bin,
                             const float* __restrict__ badd, float* __restrict__ bout,
                             int N, int K) {
    int lane = threadIdx.x & 31, w = threadIdx.x >> 5;
    int n = blockIdx.x * 8 + w;
    if (n >= N) return;
    float s = 0.f;
    for (int k = lane; k < K; k += 32) s += W[(size_t)n * K + k] * bin[k];
    #pragma unroll
    for (int off = 16; off > 0; off >>= 1) s += __shfl_xor_sync(0xffffffffu, s, off);
    if (lane == 0) bout[n] = s + (badd ? badd[n] : 0.f);
}

// ---------------- fused dt + conv + SSM + gate + RMSNorm ---------------------
// scalar fast_silu (R12 form); factored segment exponentials.
#define CDP 1282
#define MAMBA_SMEM 94336
__global__ void __launch_bounds__(512)
mamba_fused(const __nv_bfloat16* __restrict__ zx, const float* __restrict__ bi,
            const float* __restrict__ cw, const float* __restrict__ cb,
            const float* __restrict__ dt_bias, const float* __restrict__ A_log,
            const float* __restrict__ Dv, __nv_bfloat16* __restrict__ yb)
{
    extern __shared__ char sm[];
    __nv_bfloat16* sx = (__nv_bfloat16*)sm;                 // [16][1282]
    __nv_bfloat16* sy = (__nv_bfloat16*)(sm + 41024);       // [16][1024]
    float* sW     = (float*)(sm + 73792);                   // [16][16][16]
    float* sScore = (float*)(sm + 90176);
    float* sDt    = (float*)(sm + 91200);
    float* sEl    = (float*)(sm + 92224);
    float* sEdt   = (float*)(sm + 93248);
    float* sSq    = (float*)(sm + 94272);
    const int s = blockIdx.x, tid = threadIdx.x;
    const __nv_bfloat16* zb = zx + (size_t)s * L_ * D_IN_PROJ;

    if (tid < 256) {
        int l = tid >> 4, h = tid & 15;
        float v = __bfloat162float(zb[(size_t)l * D_IN_PROJ + 2304 + h]) + bi[2304 + h] + dt_bias[h];
        sDt[l * 16 + h] = (v > 20.f) ? v : log1pf(__expf(v));
    }
    if (tid < 16) sSq[tid] = 0.f;

    for (int c = tid; c < CONV_DIM; c += 512) {
        float w0 = cw[c*4], w1 = cw[c*4+1], w2 = cw[c*4+2], w3 = cw[c*4+3];
        float bb = cb[c];
        float bic = bi[D_INNER + c];
        float v0 = 0.f, v1 = 0.f, v2 = 0.f;
        const __nv_bfloat16* base = zb + D_INNER + c;
        #pragma unroll
        for (int l = 0; l < L_; ++l) {
            float v3 = __bfloat162float(base[(size_t)l * D_IN_PROJ]) + bic;
            float o = v0*w0 + v1*w1 + v2*w2 + v3*w3 + bb;
            sx[l * CDP + c] = __float2bfloat16(fast_silu(o));
            v0 = v1; v1 = v2; v2 = v3;
        }
    }
    __syncthreads();

    if (tid < 256) {
        int l = tid >> 4, sp = tid & 15;
        float acc = 0.f;
        #pragma unroll 8
        for (int n = 0; n < D_STATE; ++n)
            acc += __bfloat162float(sx[l * CDP + D_INNER + D_STATE + n])
                 * __bfloat162float(sx[sp * CDP + D_INNER + n]);
        sScore[l * 16 + sp] = acc;
    } else if (tid < 272) {
        int h = tid - 256;
        float a = -expf(A_log[h]);
        float run = 0.f;
        #pragma unroll
        for (int l = 0; l < L_; ++l) {
            run += sDt[l * 16 + h] * a;
            sEl [l * 16 + h] = expf(run);
            sEdt[l * 16 + h] = expf(-run) * sDt[l * 16 + h];
        }
    }
    __syncthreads();

    for (int i = tid; i < NHEADS * 256; i += 512) {
        int h = i >> 8, l = (i >> 4) & 15, sp = i & 15;
        float w;
        if (sp < l)       w = sScore[l*16+sp] * (sEl[l*16+h] * sEdt[sp*16+h]);
        else if (sp == l) w = sScore[l*16+l] * sDt[l*16+h] + Dv[h];
        else              w = 0.f;
        sW[(h * 16 + l) * 16 + sp] = w;
    }
    __syncthreads();

    const int h = tid >> 5, lane = tid & 31;
    const float bz0 = bi[h * HEADDIM + lane];
    const float bz1 = bi[h * HEADDIM + lane + 32];
    float x0[L_], x1[L_];
    #pragma unroll
    for (int sp = 0; sp < L_; ++sp) {
        x0[sp] = __bfloat162float(sx[sp * CDP + h * HEADDIM + lane]);
        x1[sp] = __bfloat162float(sx[sp * CDP + h * HEADDIM + lane + 32]);
    }
    #pragma unroll
    for (int l = 0; l < L_; ++l) {
        float a0 = 0.f, a1 = 0.f;
        for (int sp = 0; sp <= l; ++sp) {
            float w = sW[(h * 16 + l) * 16 + sp];
            a0 += w * x0[sp]; a1 += w * x1[sp];
        }
        float z0 = __bfloat162float(zb[(size_t)l * D_IN_PROJ + h * HEADDIM + lane]) + bz0;
        float z1 = __bfloat162float(zb[(size_t)l * D_IN_PROJ + h * HEADDIM + lane + 32]) + bz1;
        a0 *= fast_silu(z0);
        a1 *= fast_silu(z1);
        sy[l * 1024 + h * HEADDIM + lane]      = __float2bfloat16(a0);
        sy[l * 1024 + h * HEADDIM + lane + 32] = __float2bfloat16(a1);
        float q = a0 * a0 + a1 * a1;
        #pragma unroll
        for (int off = 16; off > 0; off >>= 1) q += __shfl_xor_sync(0xffffffffu, q, off);
        if (lane == 0) atomicAdd(&sSq[l], q);
    }
    __syncthreads();
    if (tid < 16) sSq[tid] = rsqrtf(sSq[tid] / (float)D_INNER + 1e-5f);
    __syncthreads();

    __nv_bfloat16* ob = yb + (size_t)s * L_ * D_INNER;
    for (int i = tid; i < L_ * D_INNER; i += 512) {
        int l = i >> 10;
        ob[i] = __float2bfloat16(__bfloat162float(sy[i]) * sSq[l]);
    }
}

// ---------------- launch -------------------------------------------------------
extern "C" void kernel_launch(void* const* d_in, const int* in_sizes, int n_in,
                              void* d_out, int out_size) {
    const float* x          = (const float*)d_in[0];
    const float* norm_w     = (const float*)d_in[1];
    const float* norm_b     = (const float*)d_in[2];
    const float* proj_in_w  = (const float*)d_in[3];
    const float* proj_in_b  = (const float*)d_in[4];
    const float* expand_w   = (const float*)d_in[5];
    const float* expand_b   = (const float*)d_in[6];
    const float* in_proj_w  = (const float*)d_in[7];
    const float* conv_w     = (const float*)d_in[8];
    const float* conv_b     = (const float*)d_in[9];
    const float* dt_bias    = (const float*)d_in[10];
    const float* A_log      = (const float*)d_in[11];
    const float* Dv         = (const float*)d_in[12];
    const float* rms_w      = (const float*)d_in[13];
    const float* out_proj_w = (const float*)d_in[14];
    const float* collapse_w = (const float*)d_in[15];
    const float* collapse_b = (const float*)d_in[16];
    const float* proj_out_w = (const float*)d_in[17];
    const float* proj_out_b = (const float*)d_in[18];
    const float* gamma      = (const float*)d_in[19];

    __nv_bfloat16 *a0, *zxb, *yb, *w21t, *wibf, *wiall, *wf1, *opt, *wfall;
    float *b21, *bi, *bfin;
    cudaGetSymbolAddress((void**)&a0,   g_a0);   cudaGetSymbolAddress((void**)&zxb,  g_zxb);
    cudaGetSymbolAddress((void**)&yb,   g_yb);
    cudaGetSymbolAddress((void**)&w21t, g_w21t); cudaGetSymbolAddress((void**)&wibf, g_wibf);
    cudaGetSymbolAddress((void**)&wiall,g_wiall);cudaGetSymbolAddress((void**)&wf1,  g_wf1);
    cudaGetSymbolAddress((void**)&opt,  g_opt);  cudaGetSymbolAddress((void**)&wfall,g_wfall);
    cudaGetSymbolAddress((void**)&b21,  g_b21);  cudaGetSymbolAddress((void**)&bi,   g_bi);
    cudaGetSymbolAddress((void**)&bfin, g_bf);

    cudaFuncSetAttribute((const void*)tc_gemm<__nv_bfloat16,0>, cudaFuncAttributeMaxDynamicSharedMemorySize, GEMM_SMEM);
    cudaFuncSetAttribute((const void*)tc_gemm<__nv_bfloat16,1>, cudaFuncAttributeMaxDynamicSharedMemorySize, GEMM_SMEM);
    cudaFuncSetAttribute((const void*)tc_gemm_back,             cudaFuncAttributeMaxDynamicSharedMemorySize, GEMM_SMEM);
    cudaFuncSetAttribute((const void*)mamba_fused,              cudaFuncAttributeMaxDynamicSharedMemorySize, MAMBA_SMEM);

    // 1. weight prep: w21t | wibf
    { dim3 g(4864, 1, 2);
      fused_prep<<<g, 256>>>(expand_w, proj_in_w, w21t, in_proj_w, wibf); }
    // 2. single-pass GroupNorm -> a0 (token-major bf16)
    gn_fused<<<NFRM*GROUPS, 256>>>(x, norm_w, norm_b, a0);
    // 3. Wi_all = wibf @ w21t^T
    { dim3 g(NPF/128, NP2320/128);
      tc_gemm<__nv_bfloat16,0><<<g, 256, GEMM_SMEM>>>(wibf, w21t, nullptr, wiall, NP2320, C_, CEXP); }
    // 4. FRONT GEMM: zx = perm(a0) @ Wi_all^T
    { dim3 g(NP2320/128, NTOK/128);
      tc_gemm<__nv_bfloat16,1><<<g, 256, GEMM_SMEM>>>(a0, wiall, nullptr, zxb, NTOK, D_IN_PROJ, C_); }
    // 5-6. bias chain
    bfold_kernel<<<CEXP/8, 256>>>(expand_w, proj_in_b, expand_b, b21, CEXP, C_);
    bfold_kernel<<<(D_IN_PROJ+7)/8, 256>>>(in_proj_w, b21, nullptr, bi, D_IN_PROJ, CEXP);
    // 7. fused mamba
    mamba_fused<<<NSEQ, 512, MAMBA_SMEM>>>(zxb, bi, conv_w, conv_b, dt_bias, A_log, Dv, yb);
    // 8. back-weight prep (wf1 | opT | bfin)
    { dim3 g(768, 1, 3);
      back_prep<<<g, 256>>>(proj_out_w, collapse_w, collapse_b, proj_out_b,
                            out_proj_w, rms_w, wf1, opt, bfin); }
    // 9. Wf_all = wf1 @ opT^T
    { dim3 g(D_INNER/128, NPF/128);
      tc_gemm<__nv_bfloat16,0><<<g, 256, GEMM_SMEM>>>(wf1, opt, nullptr, wfall, NPF, D_INNER, CEXP); }
    // 10. BACK GEMM fused with residual+transpose -> d_out
    { dim3 g(NPF/128, NTOK/128);
      tc_gemm_back<<<g, 256, GEMM_SMEM>>>(yb, wfall, bfin, x, gamma, (float*)d_out, D_INNER); }
}